// round 13
// baseline (speedup 1.0000x reference)
#include <cuda_runtime.h>
#include <cuda_bf16.h>
#include <cuda_fp16.h>
#include <cstdint>

#define DEVI __device__ __forceinline__

constexpr int B_ = 2, S_ = 2048, H_ = 1024, N_ = 16, D_ = 64;
constexpr int MROWS = B_ * S_;             // 4096
constexpr int QKVN = 3 * N_ * D_;          // 3072
constexpr long PLANE = (long)S_ * D_;      // 131072
constexpr long MPLANE = (long)B_ * N_ * PLANE;
constexpr float L2E = 1.4426950408889634f;

// ------------- static scratch -------------
__device__ __align__(16) __half g_qkvf[3 * B_ * N_ * S_ * D_];
__device__ __align__(16) __half g_mixf[B_ * N_ * S_ * D_];
__device__ float g_cum[N_ * S_];           // pre-scaled by L2E

// ------------- helpers -------------
DEVI uint32_t sma(const void* p) { return (uint32_t)__cvta_generic_to_shared(p); }
DEVI void ldsm4(uint32_t r[4], uint32_t a) {
  asm volatile("ldmatrix.sync.aligned.m8n8.x4.shared.b16 {%0,%1,%2,%3},[%4];\n"
               : "=r"(r[0]), "=r"(r[1]), "=r"(r[2]), "=r"(r[3]) : "r"(a));
}
DEVI void ldsm4t(uint32_t r[4], uint32_t a) {
  asm volatile("ldmatrix.sync.aligned.m8n8.x4.trans.shared.b16 {%0,%1,%2,%3},[%4];\n"
               : "=r"(r[0]), "=r"(r[1]), "=r"(r[2]), "=r"(r[3]) : "r"(a));
}
DEVI void mma_h(float c[4], const uint32_t a[4], uint32_t b0, uint32_t b1) {
  asm volatile(
      "mma.sync.aligned.m16n8k16.row.col.f32.f16.f16.f32 "
      "{%0,%1,%2,%3},{%4,%5,%6,%7},{%8,%9},{%0,%1,%2,%3};\n"
      : "+f"(c[0]), "+f"(c[1]), "+f"(c[2]), "+f"(c[3])
      : "r"(a[0]), "r"(a[1]), "r"(a[2]), "r"(a[3]), "r"(b0), "r"(b1));
}
DEVI float e2(float x) { float r; asm("ex2.approx.f32 %0,%1;" : "=f"(r) : "f"(x)); return r; }
DEVI uint32_t pack2h(float lo, float hi) {
  __half2 h = __floats2half2_rn(lo, hi);
  uint32_t u; memcpy(&u, &h, 4); return u;
}
DEVI uint32_t h2ex2(uint32_t x) {
  uint32_t r; asm("ex2.approx.f16x2 %0,%1;" : "=r"(r) : "r"(x)); return r;
}
DEVI void cpa(uint32_t dst, const void* src) {
  asm volatile("cp.async.cg.shared.global [%0], [%1], 16;\n" :: "r"(dst), "l"(src));
}
DEVI void cpcommit() { asm volatile("cp.async.commit_group;\n"); }
template <int n> DEVI void cpwait() { asm volatile("cp.async.wait_group %0;\n" :: "n"(n)); }

// ------------- cumsum (scaled by L2E) -------------
__global__ void cumsum_kernel(const float* __restrict__ rpe) {
  int n = blockIdx.x, t = threadIdx.x, lane = t & 31, w = t >> 5;
  __shared__ float ws[8];
  float v[8];
  const float* row = rpe + n * S_;
#pragma unroll
  for (int j = 0; j < 8; j++) v[j] = row[t * 8 + j];
#pragma unroll
  for (int j = 1; j < 8; j++) v[j] += v[j - 1];
  float s = v[7];
#pragma unroll
  for (int o = 1; o < 32; o <<= 1) {
    float x = __shfl_up_sync(0xffffffffu, s, o);
    if (lane >= o) s += x;
  }
  if (lane == 31) ws[w] = s;
  __syncthreads();
  if (w == 0) {
    float x = (lane < 8) ? ws[lane] : 0.f;
#pragma unroll
    for (int o = 1; o < 8; o <<= 1) {
      float y = __shfl_up_sync(0xffffffffu, x, o);
      if (lane >= o) x += y;
    }
    if (lane < 8) ws[lane] = x;
  }
  __syncthreads();
  float off = s - v[7] + (w ? ws[w - 1] : 0.f);
#pragma unroll
  for (int j = 0; j < 8; j++) g_cum[n * S_ + t * 8 + j] = (v[j] + off) * L2E;
}

// ------------- GEMM with fused fp32->fp16 convert, 128x128 tile -------------
// MODE 0: A = x fp32 [4096,1024], B = qkv fp32 [1024,3072] -> g_qkvf (q scaled L2E/8)
// MODE 1: A = g_mixf fp16 (planes), B = ow fp32 [1024,1024] -> fp32 d_out
// Manual LDG->reg->STS double buffer; ONE __syncthreads per K-step.
template <int MODE>
__global__ __launch_bounds__(256) void gemm_kernel(const float* __restrict__ A32,
                                                   const float* __restrict__ B32,
                                                   float* __restrict__ outp) {
  constexpr int Nn = (MODE == 0) ? QKVN : H_;
  __shared__ __align__(16) __half sA[2][128 * 40];   // 128 x 32 (pad 40)
  __shared__ __align__(16) __half sB[2][32 * 136];   // 32 x 128 (pad 136)

  const int tid = threadIdx.x, w = tid >> 5, lane = tid & 31;
  const int wm = w & 3, wn = w >> 2;
  const int row0 = blockIdx.y * 128, col0 = blockIdx.x * 128;

  // per-thread load assignment
  const int ar = tid >> 1, ac0 = (tid & 1) * 16;   // A: row, col base (16 cols)
  const int br = tid >> 3, bc0 = (tid & 7) * 16;   // B: row, col base (16 cols)

  float4 a4[4]; uint4 a4h[2]; float4 b4[4];

  auto ldA = [&](int kt) {
    if (MODE == 0) {
      const float* p = &A32[(long)(row0 + ar) * H_ + kt + ac0];
#pragma unroll
      for (int k = 0; k < 4; k++) a4[k] = __ldg((const float4*)(p + 4 * k));
    } else {
      int kcol = kt + ac0;
      int rg = row0 + ar;
      long off = ((long)((rg >> 11) * N_ + (kcol >> 6)) * S_ + (rg & 2047)) * D_ + (kcol & 63);
      const __half* p = &g_mixf[off];
      a4h[0] = __ldg((const uint4*)p);
      a4h[1] = __ldg((const uint4*)(p + 8));
    }
  };
  auto ldB = [&](int kt) {
    const float* p = &B32[(long)(kt + br) * Nn + col0 + bc0];
#pragma unroll
    for (int k = 0; k < 4; k++) b4[k] = __ldg((const float4*)(p + 4 * k));
  };
  auto sts = [&](int st) {
    if (MODE == 0) {
      uint32_t h[8];
#pragma unroll
      for (int k = 0; k < 4; k++) {
        h[2 * k] = pack2h(a4[k].x, a4[k].y);
        h[2 * k + 1] = pack2h(a4[k].z, a4[k].w);
      }
      *(uint4*)&sA[st][ar * 40 + ac0] = *(uint4*)&h[0];
      *(uint4*)&sA[st][ar * 40 + ac0 + 8] = *(uint4*)&h[4];
    } else {
      *(uint4*)&sA[st][ar * 40 + ac0] = a4h[0];
      *(uint4*)&sA[st][ar * 40 + ac0 + 8] = a4h[1];
    }
    uint32_t h[8];
#pragma unroll
    for (int k = 0; k < 4; k++) {
      h[2 * k] = pack2h(b4[k].x, b4[k].y);
      h[2 * k + 1] = pack2h(b4[k].z, b4[k].w);
    }
    *(uint4*)&sB[st][br * 136 + bc0] = *(uint4*)&h[0];
    *(uint4*)&sB[st][br * 136 + bc0 + 8] = *(uint4*)&h[4];
  };

  float acc[2][8][4];
#pragma unroll
  for (int a = 0; a < 2; a++)
#pragma unroll
    for (int b = 0; b < 8; b++)
#pragma unroll
      for (int c = 0; c < 4; c++) acc[a][b][c] = 0.f;

  ldA(0); ldB(0);
  constexpr int NK = H_ / 32;
  for (int t = 0; t < NK; t++) {
    const int st = t & 1;
    sts(st);
    __syncthreads();
    if (t + 1 < NK) { ldA((t + 1) * 32); ldB((t + 1) * 32); }
#pragma unroll
    for (int kc = 0; kc < 2; kc++) {
      uint32_t af[2][4];
#pragma unroll
      for (int mi = 0; mi < 2; mi++) {
        int r = wm * 32 + mi * 16 + (lane & 15);
        ldsm4(af[mi], sma(&sA[st][r * 40 + kc * 16 + (lane >> 4) * 8]));
      }
#pragma unroll
      for (int pr = 0; pr < 4; pr++) {
        uint32_t b4f[4];
        int g = lane >> 3, r = lane & 7;
        int rb = kc * 16 + r + ((g & 1) ? 8 : 0);
        int cb = wn * 64 + pr * 16 + ((g >= 2) ? 8 : 0);
        ldsm4t(b4f, sma(&sB[st][rb * 136 + cb]));
#pragma unroll
        for (int mi = 0; mi < 2; mi++) {
          mma_h(acc[mi][2 * pr], af[mi], b4f[0], b4f[1]);
          mma_h(acc[mi][2 * pr + 1], af[mi], b4f[2], b4f[3]);
        }
      }
    }
  }
#pragma unroll
  for (int mi = 0; mi < 2; mi++)
#pragma unroll
    for (int nj = 0; nj < 8; nj++)
#pragma unroll
      for (int v = 0; v < 4; v++) {
        int rg = row0 + wm * 32 + mi * 16 + (lane >> 2) + ((v & 2) ? 8 : 0);
        int c = col0 + wn * 64 + nj * 8 + 2 * (lane & 3) + (v & 1);
        float val = acc[mi][nj][v];
        if (MODE == 0) {
          int m = c >> 10, nh = (c >> 6) & 15, d = c & 63;
          if (m == 0) val *= 0.125f * L2E;
          int b = rg >> 11, s = rg & 2047;
          long idx = ((long)(m * 32 + b * 16 + nh)) * PLANE + (long)s * D_ + d;
          g_qkvf[idx] = __float2half_rn(val);
        } else {
          outp[(long)rg * H_ + c] = val;
        }
      }
}

// ------------- causal flash attention, 128-key staged tiles, dynamic smem -------------
// dyn smem: ring of 2 stages x (K 128x72 + V 128x72) halves = 73728 B; Q overlaps stage 0.
__global__ __launch_bounds__(256, 2) void flash_kernel() {
  extern __shared__ __align__(16) __half dsm[];
  __shared__ float sBias[256];
  const int qt = 15 - blockIdx.x;
  const int bh = blockIdx.y;
  const int n = bh & 15;
  const int q0 = qt * 128;
  const int tid = threadIdx.x, w = tid >> 5, lane = tid & 31;

  __half* sQ = dsm;
#define SK(st) (dsm + (st) * 18432)
#define SV(st) (dsm + (st) * 18432 + 9216)

  const long pl = (long)bh * PLANE;
  const __half* qg = g_qkvf + pl;
  const __half* kg = g_qkvf + MPLANE + pl;
  const __half* vg = g_qkvf + 2 * MPLANE + pl;

#pragma unroll
  for (int p = 0; p < 4; p++) {
    int i = tid + 256 * p;
    int r = i >> 3, c8 = i & 7;
    *(uint4*)&sQ[r * 72 + c8 * 8] = *(const uint4*)&qg[(long)(q0 + r) * D_ + c8 * 8];
  }
  __syncthreads();
  uint32_t qf[4][4];
  {
    int r = w * 16 + (lane & 15), cb = (lane >> 4) * 8;
#pragma unroll
    for (int kc = 0; kc < 4; kc++) ldsm4(qf[kc], sma(&sQ[r * 72 + kc * 16 + cb]));
  }
  __syncthreads();

  float Oa[8][4];
#pragma unroll
  for (int j = 0; j < 8; j++)
#pragma unroll
    for (int v = 0; v < 4; v++) Oa[j][v] = 0.f;
  float mrow[2] = {-1e30f, -1e30f}, lrow[2] = {0.f, 0.f};
  const float* cumn = g_cum + n * S_;
  const int ntiles = qt + 1;                 // 128-key tiles
  const int itop = q0 + w * 16 + 15;
  const int ibase = w * 16 + (lane >> 2) + 63 - 2 * (lane & 3);
  constexpr uint32_t ONE2 = 0x3C003C00u;

  auto loadkv = [&](int st, int t) {
    int kv0 = t * 128;
#pragma unroll
    for (int p = 0; p < 4; p++) {
      int i = tid + 256 * p;
      int r = i >> 3, c8 = i & 7;
      long g = (long)(kv0 + r) * D_ + c8 * 8;
      cpa(sma(SK(st) + r * 72 + c8 * 8), kg + g);
      cpa(sma(SV(st) + r * 72 + c8 * 8), vg + g);
    }
  };

  loadkv(0, 0);
  cpcommit();
  for (int t = 0; t < ntiles; t++) {
    const int kv0 = t * 128;
    if (t + 1 < ntiles) loadkv((t + 1) & 1, t + 1);
    cpcommit();
    {  // bias window covers both halves: sBias[i] = cum[q0-kv0-127+i]
      int src = q0 - kv0 - 127 + tid;
      sBias[tid] = (src >= 0) ? cumn[src] : 0.f;
    }
    cpwait<1>();
    __syncthreads();
    const int st = t & 1;
#pragma unroll
    for (int h = 0; h < 2; h++) {
      const int kvh = kv0 + 64 * h;
      if (kvh > itop) continue;
      const __half* sk = SK(st) + 64 * h * 72;
      const __half* sv = SV(st) + 64 * h * 72;
      float sc[8][4];
#pragma unroll
      for (int j = 0; j < 8; j++)
#pragma unroll
        for (int v = 0; v < 4; v++) sc[j][v] = 0.f;
#pragma unroll
      for (int kc = 0; kc < 4; kc++) {
#pragma unroll
        for (int pr = 0; pr < 4; pr++) {
          uint32_t b4[4];
          int g = lane >> 3, r = lane & 7;
          int rk = pr * 16 + r + ((g >= 2) ? 8 : 0);
          int ck = kc * 16 + ((g & 1) ? 8 : 0);
          ldsm4(b4, sma(sk + rk * 72 + ck));
          mma_h(sc[2 * pr], qf[kc], b4[0], b4[1]);
          mma_h(sc[2 * pr + 1], qf[kc], b4[2], b4[3]);
        }
      }
      const bool full = (kvh + 63 <= q0 + w * 16);
      const int dshift = q0 - kvh - 63;
      const int boff = 64 - 64 * h;  // sBias index = local idx + boff
      float mx[2] = {-1e30f, -1e30f};
      if (full) {
#pragma unroll
        for (int j = 0; j < 8; j++)
#pragma unroll
          for (int v = 0; v < 4; v++) {
            int idx = ibase + ((v & 2) ? 8 : 0) - j * 8 - (v & 1);
            float s = sc[j][v] + sBias[idx + boff];
            sc[j][v] = s;
            mx[v >> 1] = fmaxf(mx[v >> 1], s);
          }
      } else {
#pragma unroll
        for (int j = 0; j < 8; j++)
#pragma unroll
          for (int v = 0; v < 4; v++) {
            int idx = ibase + ((v & 2) ? 8 : 0) - j * 8 - (v & 1);
            float s = (dshift + idx < 0) ? -1e30f : sc[j][v] + sBias[idx + boff];
            sc[j][v] = s;
            mx[v >> 1] = fmaxf(mx[v >> 1], s);
          }
      }
#pragma unroll
      for (int hh = 0; hh < 2; hh++) {
        mx[hh] = fmaxf(mx[hh], __shfl_xor_sync(0xffffffffu, mx[hh], 1));
        mx[hh] = fmaxf(mx[hh], __shfl_xor_sync(0xffffffffu, mx[hh], 2));
      }
      float al[2];
#pragma unroll
      for (int hh = 0; hh < 2; hh++) {
        float mn = fmaxf(mrow[hh], mx[hh]);
        al[hh] = e2(mrow[hh] - mn);
        mrow[hh] = mn;
      }
      uint32_t ap[4][4];
#pragma unroll
      for (int kc = 0; kc < 4; kc++) {
        ap[kc][0] = h2ex2(pack2h(sc[2 * kc][0] - mrow[0], sc[2 * kc][1] - mrow[0]));
        ap[kc][1] = h2ex2(pack2h(sc[2 * kc][2] - mrow[1], sc[2 * kc][3] - mrow[1]));
        ap[kc][2] = h2ex2(pack2h(sc[2 * kc + 1][0] - mrow[0], sc[2 * kc + 1][1] - mrow[0]));
        ap[kc][3] = h2ex2(pack2h(sc[2 * kc + 1][2] - mrow[1], sc[2 * kc + 1][3] - mrow[1]));
      }
      float ps[4] = {0.f, 0.f, 0.f, 0.f};
#pragma unroll
      for (int kc = 0; kc < 4; kc++) mma_h(ps, ap[kc], ONE2, ONE2);
      lrow[0] = lrow[0] * al[0] + ps[0];
      lrow[1] = lrow[1] * al[1] + ps[2];
#pragma unroll
      for (int j = 0; j < 8; j++)
#pragma unroll
        for (int v = 0; v < 4; v++) Oa[j][v] *= al[v >> 1];
#pragma unroll
      for (int kc = 0; kc < 4; kc++) {
#pragma unroll
        for (int pr = 0; pr < 4; pr++) {
          uint32_t b4[4];
          int g = lane >> 3, r = lane & 7;
          int rv = kc * 16 + r + ((g & 1) ? 8 : 0);
          int cv = pr * 16 + ((g >= 2) ? 8 : 0);
          ldsm4t(b4, sma(sv + rv * 72 + cv));
          mma_h(Oa[2 * pr], ap[kc], b4[0], b4[1]);
          mma_h(Oa[2 * pr + 1], ap[kc], b4[2], b4[3]);
        }
      }
    }
    __syncthreads();
  }
  float inv[2] = {1.f / lrow[0], 1.f / lrow[1]};
  __half* mf = g_mixf + pl;
#pragma unroll
  for (int j = 0; j < 8; j++)
#pragma unroll
    for (int v = 0; v < 2; v++) {
      int ii = q0 + w * 16 + (lane >> 2) + v * 8;
      int d = j * 8 + 2 * (lane & 3);
      __half2 h = __floats2half2_rn(Oa[j][2 * v] * inv[v], Oa[j][2 * v + 1] * inv[v]);
      *(__half2*)&mf[(long)ii * D_ + d] = h;
    }
}

// ------------- launch -------------
extern "C" void kernel_launch(void* const* d_in, const int* in_sizes, int n_in,
                              void* d_out, int out_size) {
  const float* x = (const float*)d_in[0];
  const float* qkv = (const float*)d_in[1];
  const float* ow = (const float*)d_in[2];
  const float* rpe = (const float*)d_in[3];
  float* out = (float*)d_out;

  static bool attr_done = false;
  if (!attr_done) {
    cudaFuncSetAttribute(flash_kernel, cudaFuncAttributeMaxDynamicSharedMemorySize, 73728);
    attr_done = true;
  }

  cumsum_kernel<<<16, 256>>>(rpe);
  gemm_kernel<0><<<dim3(QKVN / 128, MROWS / 128), 256>>>(x, qkv, nullptr);
  flash_kernel<<<dim3(16, B_ * N_), 256, 73728>>>();
  gemm_kernel<1><<<dim3(H_ / 128, MROWS / 128), 256>>>(nullptr, ow, out);
}

// round 15
// speedup vs baseline: 1.3299x; 1.3299x over previous
#include <cuda_runtime.h>
#include <cuda_bf16.h>
#include <cuda_fp16.h>
#include <cstdint>

#define DEVI __device__ __forceinline__

constexpr int B_ = 2, S_ = 2048, H_ = 1024, N_ = 16, D_ = 64;
constexpr int MROWS = B_ * S_;             // 4096
constexpr int QKVN = 3 * N_ * D_;          // 3072
constexpr long PLANE = (long)S_ * D_;      // 131072
constexpr long MPLANE = (long)B_ * N_ * PLANE;
constexpr float L2E = 1.4426950408889634f;
constexpr int XN = MROWS * H_;
constexpr int WN = H_ * QKVN;
constexpr int OWN = H_ * H_;

// ------------- static scratch -------------
__device__ __align__(16) __half g_xf[XN];
__device__ __align__(16) __half g_wf[WN];
__device__ __align__(16) __half g_owf[OWN];
__device__ __align__(16) __half g_qkvf[3 * B_ * N_ * S_ * D_];
__device__ __align__(16) __half g_mixf[B_ * N_ * S_ * D_];
__device__ float g_cum[N_ * S_];           // pre-scaled by L2E

// ------------- helpers -------------
DEVI uint32_t sma(const void* p) { return (uint32_t)__cvta_generic_to_shared(p); }
DEVI void ldsm4(uint32_t r[4], uint32_t a) {
  asm volatile("ldmatrix.sync.aligned.m8n8.x4.shared.b16 {%0,%1,%2,%3},[%4];\n"
               : "=r"(r[0]), "=r"(r[1]), "=r"(r[2]), "=r"(r[3]) : "r"(a));
}
DEVI void ldsm4t(uint32_t r[4], uint32_t a) {
  asm volatile("ldmatrix.sync.aligned.m8n8.x4.trans.shared.b16 {%0,%1,%2,%3},[%4];\n"
               : "=r"(r[0]), "=r"(r[1]), "=r"(r[2]), "=r"(r[3]) : "r"(a));
}
DEVI void mma_h(float c[4], const uint32_t a[4], uint32_t b0, uint32_t b1) {
  asm volatile(
      "mma.sync.aligned.m16n8k16.row.col.f32.f16.f16.f32 "
      "{%0,%1,%2,%3},{%4,%5,%6,%7},{%8,%9},{%0,%1,%2,%3};\n"
      : "+f"(c[0]), "+f"(c[1]), "+f"(c[2]), "+f"(c[3])
      : "r"(a[0]), "r"(a[1]), "r"(a[2]), "r"(a[3]), "r"(b0), "r"(b1));
}
DEVI float e2(float x) { float r; asm("ex2.approx.f32 %0,%1;" : "=f"(r) : "f"(x)); return r; }
DEVI uint32_t pack2h(float lo, float hi) {
  __half2 h = __floats2half2_rn(lo, hi);
  uint32_t u; memcpy(&u, &h, 4); return u;
}
DEVI uint32_t h2ex2(uint32_t x) {
  uint32_t r; asm("ex2.approx.f16x2 %0,%1;" : "=r"(r) : "r"(x)); return r;
}
DEVI void cpa(uint32_t dst, const void* src) {
  asm volatile("cp.async.cg.shared.global [%0], [%1], 16;\n" :: "r"(dst), "l"(src));
}
DEVI void cpcommit() { asm volatile("cp.async.commit_group;\n"); }
template <int n> DEVI void cpwait() { asm volatile("cp.async.wait_group %0;\n" :: "n"(n)); }

// ------------- fused convert -------------
__global__ void convert_all_kernel(const float* __restrict__ x,
                                   const float* __restrict__ qkv,
                                   const float* __restrict__ ow) {
  long i = (long)(blockIdx.x * blockDim.x + threadIdx.x) * 4;
  const float* src;
  __half* dst;
  long off;
  if (i < XN) { src = x; dst = g_xf; off = i; }
  else if (i < XN + WN) { src = qkv; dst = g_wf; off = i - XN; }
  else if (i < XN + WN + OWN) { src = ow; dst = g_owf; off = i - XN - WN; }
  else return;
  float4 v = *(const float4*)&src[off];
  *(__half2*)&dst[off] = __floats2half2_rn(v.x, v.y);
  *(__half2*)&dst[off + 2] = __floats2half2_rn(v.z, v.w);
}

// ------------- cumsum (scaled by L2E) -------------
__global__ void cumsum_kernel(const float* __restrict__ rpe) {
  int n = blockIdx.x, t = threadIdx.x, lane = t & 31, w = t >> 5;
  __shared__ float ws[8];
  float v[8];
  const float* row = rpe + n * S_;
#pragma unroll
  for (int j = 0; j < 8; j++) v[j] = row[t * 8 + j];
#pragma unroll
  for (int j = 1; j < 8; j++) v[j] += v[j - 1];
  float s = v[7];
#pragma unroll
  for (int o = 1; o < 32; o <<= 1) {
    float x = __shfl_up_sync(0xffffffffu, s, o);
    if (lane >= o) s += x;
  }
  if (lane == 31) ws[w] = s;
  __syncthreads();
  if (w == 0) {
    float x = (lane < 8) ? ws[lane] : 0.f;
#pragma unroll
    for (int o = 1; o < 8; o <<= 1) {
      float y = __shfl_up_sync(0xffffffffu, x, o);
      if (lane >= o) x += y;
    }
    if (lane < 8) ws[lane] = x;
  }
  __syncthreads();
  float off = s - v[7] + (w ? ws[w - 1] : 0.f);
#pragma unroll
  for (int j = 0; j < 8; j++) g_cum[n * S_ + t * 8 + j] = (v[j] + off) * L2E;
}

// ------------- fp16 GEMM, 128x128 tile, cp.async 2-stage, K-step 32 -------------
// MODE 0: x[4096,1024]@w[1024,3072] -> fp16 q/k/v planes (q scaled L2E/8)
// MODE 1: mix(planes)[4096,1024]@ow[1024,1024] -> fp32 d_out
template <int MODE>
__global__ __launch_bounds__(256) void gemm_kernel(float* __restrict__ outp) {
  constexpr int Nn = (MODE == 0) ? QKVN : H_;
  const __half* __restrict__ Ag = (MODE == 0) ? g_xf : g_mixf;
  const __half* __restrict__ Bg = (MODE == 0) ? g_wf : g_owf;

  __shared__ __align__(16) __half sA[2][128 * 40];   // 128 x 32 (pad 40)
  __shared__ __align__(16) __half sB[2][32 * 136];   // 32 x 128 (pad 136)

  const int tid = threadIdx.x, w = tid >> 5, lane = tid & 31;
  const int wm = w & 3, wn = w >> 2;
  const int row0 = blockIdx.y * 128, col0 = blockIdx.x * 128;

  float acc[2][8][4];
#pragma unroll
  for (int a = 0; a < 2; a++)
#pragma unroll
    for (int b = 0; b < 8; b++)
#pragma unroll
      for (int c = 0; c < 4; c++) acc[a][b][c] = 0.f;

  auto load_tile = [&](int st, int kt) {
#pragma unroll
    for (int p = 0; p < 2; p++) {  // A 128x32
      int i = tid + 256 * p;
      int r = i >> 2, seg = i & 3;
      int rg = row0 + r;
      long off;
      if (MODE == 0) {
        off = (long)rg * H_ + kt + seg * 8;
      } else {
        int k = kt + seg * 8;
        off = ((long)((rg >> 11) * N_ + (k >> 6)) * S_ + (rg & 2047)) * D_ + (k & 63);
      }
      cpa(sma(&sA[st][r * 40 + seg * 8]), &Ag[off]);
    }
#pragma unroll
    for (int p = 0; p < 2; p++) {  // B 32x128
      int i = tid + 256 * p;
      int r = i >> 4, c8 = i & 15;
      cpa(sma(&sB[st][r * 136 + c8 * 8]), &Bg[(long)(kt + r) * Nn + col0 + c8 * 8]);
    }
  };

  load_tile(0, 0);
  cpcommit();
  constexpr int NK = H_ / 32;
  for (int t = 0; t < NK; t++) {
    if (t + 1 < NK) load_tile((t + 1) & 1, (t + 1) * 32);
    cpcommit();
    cpwait<1>();
    __syncthreads();
    const int st = t & 1;
#pragma unroll
    for (int kc = 0; kc < 2; kc++) {
      uint32_t af[2][4];
#pragma unroll
      for (int mi = 0; mi < 2; mi++) {
        int r = wm * 32 + mi * 16 + (lane & 15);
        ldsm4(af[mi], sma(&sA[st][r * 40 + kc * 16 + (lane >> 4) * 8]));
      }
#pragma unroll
      for (int pr = 0; pr < 4; pr++) {
        uint32_t b4[4];
        int g = lane >> 3, r = lane & 7;
        int rb = kc * 16 + r + ((g & 1) ? 8 : 0);
        int cb = wn * 64 + pr * 16 + ((g >= 2) ? 8 : 0);
        ldsm4t(b4, sma(&sB[st][rb * 136 + cb]));
#pragma unroll
        for (int mi = 0; mi < 2; mi++) {
          mma_h(acc[mi][2 * pr], af[mi], b4[0], b4[1]);
          mma_h(acc[mi][2 * pr + 1], af[mi], b4[2], b4[3]);
        }
      }
    }
    __syncthreads();
  }
#pragma unroll
  for (int mi = 0; mi < 2; mi++)
#pragma unroll
    for (int nj = 0; nj < 8; nj++)
#pragma unroll
      for (int v = 0; v < 4; v++) {
        int rg = row0 + wm * 32 + mi * 16 + (lane >> 2) + ((v & 2) ? 8 : 0);
        int c = col0 + wn * 64 + nj * 8 + 2 * (lane & 3) + (v & 1);
        float val = acc[mi][nj][v];
        if (MODE == 0) {
          int m = c >> 10, nh = (c >> 6) & 15, d = c & 63;
          if (m == 0) val *= 0.125f * L2E;
          int b = rg >> 11, s = rg & 2047;
          long idx = ((long)(m * 32 + b * 16 + nh)) * PLANE + (long)s * D_ + d;
          g_qkvf[idx] = __float2half_rn(val);
        } else {
          outp[(long)rg * H_ + c] = val;
        }
      }
}

// ------------- causal flash attention: 3-stage KV ring, ONE sync per tile -------------
// dyn smem: 3 stages x (K 64x72 + V 64x72) = 3*9216 halves = 55296 B; Q overlaps stage 0+1.
__global__ __launch_bounds__(256, 2) void flash_kernel() {
  extern __shared__ __align__(16) __half dsm[];
  __shared__ float sBias[2][192];
  const int qt = 15 - blockIdx.x;
  const int bh = blockIdx.y;
  const int n = bh & 15;
  const int q0 = qt * 128;
  const int tid = threadIdx.x, w = tid >> 5, lane = tid & 31;

  __half* sQ = dsm;  // 128x72 = 9216 halves (stage 0+1 region)
#define SK(st) (dsm + (st) * 9216)
#define SV(st) (dsm + (st) * 9216 + 4608)

  const long pl = (long)bh * PLANE;
  const __half* qg = g_qkvf + pl;
  const __half* kg = g_qkvf + MPLANE + pl;
  const __half* vg = g_qkvf + 2 * MPLANE + pl;

#pragma unroll
  for (int p = 0; p < 4; p++) {
    int i = tid + 256 * p;
    int r = i >> 3, c8 = i & 7;
    *(uint4*)&sQ[r * 72 + c8 * 8] = *(const uint4*)&qg[(long)(q0 + r) * D_ + c8 * 8];
  }
  __syncthreads();
  uint32_t qf[4][4];
  {
    int r = w * 16 + (lane & 15), cb = (lane >> 4) * 8;
#pragma unroll
    for (int kc = 0; kc < 4; kc++) ldsm4(qf[kc], sma(&sQ[r * 72 + kc * 16 + cb]));
  }
  __syncthreads();  // Q consumed; KV ring may overwrite

  float Oa[8][4];
#pragma unroll
  for (int j = 0; j < 8; j++)
#pragma unroll
    for (int v = 0; v < 4; v++) Oa[j][v] = 0.f;
  float mrow[2] = {-1e30f, -1e30f}, lrow[2] = {0.f, 0.f};
  const float* cumn = g_cum + n * S_;
  const int ntiles = 2 * qt + 2;
  const int itop = q0 + w * 16 + 15;
  const int ibase = w * 16 + (lane >> 2) + 63 - 2 * (lane & 3);
  constexpr uint32_t ONE2 = 0x3C003C00u;

  auto loadkv = [&](int st, int t) {
    int kv0 = t * 64;
#pragma unroll
    for (int p = 0; p < 2; p++) {
      int i = tid + 256 * p;
      int r = i >> 3, c8 = i & 7;
      long g = (long)(kv0 + r) * D_ + c8 * 8;
      cpa(sma(SK(st) + r * 72 + c8 * 8), kg + g);
      cpa(sma(SV(st) + r * 72 + c8 * 8), vg + g);
    }
  };
  auto stage_bias = [&](int buf, int t) {  // sBias[buf][i] = cum[q0 - 64t - 63 + i]
    if (tid < 192) {
      int src = q0 - t * 64 - 63 + tid;
      sBias[buf][tid] = (src >= 0) ? cumn[src] : 0.f;
    }
  };

  // prologue: tiles 0 and 1 in flight; bias for tile 0 staged
  loadkv(0, 0);
  cpcommit();
  loadkv(1, 1);  // ntiles >= 2 always
  cpcommit();
  stage_bias(0, 0);

  for (int t = 0; t < ntiles; t++) {
    const int kv0 = t * 64;
    cpwait<1>();       // tile t landed (tile t+1 may still be in flight)
    __syncthreads();   // all warps done with tile t-1; bias[t&1] visible
    // refill: stage (t+2)%3 was last read at tile t-1 -> safe now
    if (t + 2 < ntiles) loadkv((t + 2) % 3, t + 2);
    cpcommit();
    if (t + 1 < ntiles) stage_bias((t + 1) & 1, t + 1);  // readers of this buf finished t-1
    const int st = t % 3;
    if (kv0 <= itop) {
      const float* bias = sBias[t & 1];
      float sc[8][4];
#pragma unroll
      for (int j = 0; j < 8; j++)
#pragma unroll
        for (int v = 0; v < 4; v++) sc[j][v] = 0.f;
#pragma unroll
      for (int kc = 0; kc < 4; kc++) {
#pragma unroll
        for (int pr = 0; pr < 4; pr++) {
          uint32_t b4[4];
          int g = lane >> 3, r = lane & 7;
          int rk = pr * 16 + r + ((g >= 2) ? 8 : 0);
          int ck = kc * 16 + ((g & 1) ? 8 : 0);
          ldsm4(b4, sma(SK(st) + rk * 72 + ck));
          mma_h(sc[2 * pr], qf[kc], b4[0], b4[1]);
          mma_h(sc[2 * pr + 1], qf[kc], b4[2], b4[3]);
        }
      }
      const bool full = (kv0 + 63 <= q0 + w * 16);
      const int dshift = q0 - kv0 - 63;
      float mx[2] = {-1e30f, -1e30f};
      if (full) {
#pragma unroll
        for (int j = 0; j < 8; j++)
#pragma unroll
          for (int v = 0; v < 4; v++) {
            int idx = ibase + ((v & 2) ? 8 : 0) - j * 8 - (v & 1);
            float s = sc[j][v] + bias[idx];
            sc[j][v] = s;
            mx[v >> 1] = fmaxf(mx[v >> 1], s);
          }
      } else {
#pragma unroll
        for (int j = 0; j < 8; j++)
#pragma unroll
          for (int v = 0; v < 4; v++) {
            int idx = ibase + ((v & 2) ? 8 : 0) - j * 8 - (v & 1);
            float s = (dshift + idx < 0) ? -1e30f : sc[j][v] + bias[idx];
            sc[j][v] = s;
            mx[v >> 1] = fmaxf(mx[v >> 1], s);
          }
      }
#pragma unroll
      for (int h = 0; h < 2; h++) {
        mx[h] = fmaxf(mx[h], __shfl_xor_sync(0xffffffffu, mx[h], 1));
        mx[h] = fmaxf(mx[h], __shfl_xor_sync(0xffffffffu, mx[h], 2));
      }
      float al[2];
#pragma unroll
      for (int h = 0; h < 2; h++) {
        float mn = fmaxf(mrow[h], mx[h]);
        al[h] = e2(mrow[h] - mn);
        mrow[h] = mn;
      }
      uint32_t ap[4][4];
#pragma unroll
      for (int kc = 0; kc < 4; kc++) {
        ap[kc][0] = h2ex2(pack2h(sc[2 * kc][0] - mrow[0], sc[2 * kc][1] - mrow[0]));
        ap[kc][1] = h2ex2(pack2h(sc[2 * kc][2] - mrow[1], sc[2 * kc][3] - mrow[1]));
        ap[kc][2] = h2ex2(pack2h(sc[2 * kc + 1][0] - mrow[0], sc[2 * kc + 1][1] - mrow[0]));
        ap[kc][3] = h2ex2(pack2h(sc[2 * kc + 1][2] - mrow[1], sc[2 * kc + 1][3] - mrow[1]));
      }
      float ps[4] = {0.f, 0.f, 0.f, 0.f};
#pragma unroll
      for (int kc = 0; kc < 4; kc++) mma_h(ps, ap[kc], ONE2, ONE2);
      lrow[0] = lrow[0] * al[0] + ps[0];
      lrow[1] = lrow[1] * al[1] + ps[2];
#pragma unroll
      for (int j = 0; j < 8; j++)
#pragma unroll
        for (int v = 0; v < 4; v++) Oa[j][v] *= al[v >> 1];
#pragma unroll
      for (int kc = 0; kc < 4; kc++) {
#pragma unroll
        for (int pr = 0; pr < 4; pr++) {
          uint32_t b4[4];
          int g = lane >> 3, r = lane & 7;
          int rv = kc * 16 + r + ((g & 1) ? 8 : 0);
          int cv = pr * 16 + ((g >= 2) ? 8 : 0);
          ldsm4t(b4, sma(SV(st) + rv * 72 + cv));
          mma_h(Oa[2 * pr], ap[kc], b4[0], b4[1]);
          mma_h(Oa[2 * pr + 1], ap[kc], b4[2], b4[3]);
        }
      }
    }
  }
  float inv[2] = {1.f / lrow[0], 1.f / lrow[1]};
  __half* mf = g_mixf + pl;
#pragma unroll
  for (int j = 0; j < 8; j++)
#pragma unroll
    for (int v = 0; v < 2; v++) {
      int ii = q0 + w * 16 + (lane >> 2) + v * 8;
      int d = j * 8 + 2 * (lane & 3);
      __half2 h = __floats2half2_rn(Oa[j][2 * v] * inv[v], Oa[j][2 * v + 1] * inv[v]);
      *(__half2*)&mf[(long)ii * D_ + d] = h;
    }
}

// ------------- launch -------------
extern "C" void kernel_launch(void* const* d_in, const int* in_sizes, int n_in,
                              void* d_out, int out_size) {
  const float* x = (const float*)d_in[0];
  const float* qkv = (const float*)d_in[1];
  const float* ow = (const float*)d_in[2];
  const float* rpe = (const float*)d_in[3];
  float* out = (float*)d_out;

  static bool attr_done = false;
  if (!attr_done) {
    cudaFuncSetAttribute(flash_kernel, cudaFuncAttributeMaxDynamicSharedMemorySize, 55296);
    attr_done = true;
  }

  convert_all_kernel<<<(XN + WN + OWN) / 4 / 256, 256>>>(x, qkv, ow);
  cumsum_kernel<<<16, 256>>>(rpe);
  gemm_kernel<0><<<dim3(QKVN / 128, MROWS / 128), 256>>>(nullptr);
  flash_kernel<<<dim3(16, B_ * N_), 256, 55296>>>();
  gemm_kernel<1><<<dim3(H_ / 128, MROWS / 128), 256>>>(out);
}

// round 17
// speedup vs baseline: 1.4482x; 1.0889x over previous
#include <cuda_runtime.h>
#include <cuda_bf16.h>
#include <cuda_fp16.h>
#include <cstdint>

#define DEVI __device__ __forceinline__

constexpr int B_ = 2, S_ = 2048, H_ = 1024, N_ = 16, D_ = 64;
constexpr int MROWS = B_ * S_;             // 4096
constexpr int QKVN = 3 * N_ * D_;          // 3072
constexpr long PLANE = (long)S_ * D_;      // 131072
constexpr long MPLANE = (long)B_ * N_ * PLANE;
constexpr float L2E = 1.4426950408889634f;
constexpr int XN = MROWS * H_;
constexpr int WN = H_ * QKVN;
constexpr int OWN = H_ * H_;

// ------------- static scratch -------------
__device__ __align__(16) __half g_xf[XN];
__device__ __align__(16) __half g_wf[WN];
__device__ __align__(16) __half g_owf[OWN];
__device__ __align__(16) __half g_qkvf[3 * B_ * N_ * S_ * D_];
__device__ __align__(16) __half g_mixf[B_ * N_ * S_ * D_];
__device__ float g_cum[N_ * S_];           // pre-scaled by L2E

// ------------- helpers -------------
DEVI uint32_t sma(const void* p) { return (uint32_t)__cvta_generic_to_shared(p); }
DEVI void ldsm4(uint32_t r[4], uint32_t a) {
  asm volatile("ldmatrix.sync.aligned.m8n8.x4.shared.b16 {%0,%1,%2,%3},[%4];\n"
               : "=r"(r[0]), "=r"(r[1]), "=r"(r[2]), "=r"(r[3]) : "r"(a));
}
DEVI void ldsm4t(uint32_t r[4], uint32_t a) {
  asm volatile("ldmatrix.sync.aligned.m8n8.x4.trans.shared.b16 {%0,%1,%2,%3},[%4];\n"
               : "=r"(r[0]), "=r"(r[1]), "=r"(r[2]), "=r"(r[3]) : "r"(a));
}
DEVI void mma_h(float c[4], const uint32_t a[4], uint32_t b0, uint32_t b1) {
  asm volatile(
      "mma.sync.aligned.m16n8k16.row.col.f32.f16.f16.f32 "
      "{%0,%1,%2,%3},{%4,%5,%6,%7},{%8,%9},{%0,%1,%2,%3};\n"
      : "+f"(c[0]), "+f"(c[1]), "+f"(c[2]), "+f"(c[3])
      : "r"(a[0]), "r"(a[1]), "r"(a[2]), "r"(a[3]), "r"(b0), "r"(b1));
}
DEVI float e2(float x) { float r; asm("ex2.approx.f32 %0,%1;" : "=f"(r) : "f"(x)); return r; }
DEVI uint32_t pack2h(float lo, float hi) {
  __half2 h = __floats2half2_rn(lo, hi);
  uint32_t u; memcpy(&u, &h, 4); return u;
}
DEVI uint32_t h2ex2(uint32_t x) {
  uint32_t r; asm("ex2.approx.f16x2 %0,%1;" : "=r"(r) : "r"(x)); return r;
}
DEVI void cpa(uint32_t dst, const void* src) {
  asm volatile("cp.async.cg.shared.global [%0], [%1], 16;\n" :: "r"(dst), "l"(src));
}
DEVI void cpcommit() { asm volatile("cp.async.commit_group;\n"); }
template <int n> DEVI void cpwait() { asm volatile("cp.async.wait_group %0;\n" :: "n"(n)); }

// ------------- fused convert -------------
__global__ void convert_all_kernel(const float* __restrict__ x,
                                   const float* __restrict__ qkv,
                                   const float* __restrict__ ow) {
  long i = (long)(blockIdx.x * blockDim.x + threadIdx.x) * 4;
  const float* src;
  __half* dst;
  long off;
  if (i < XN) { src = x; dst = g_xf; off = i; }
  else if (i < XN + WN) { src = qkv; dst = g_wf; off = i - XN; }
  else if (i < XN + WN + OWN) { src = ow; dst = g_owf; off = i - XN - WN; }
  else return;
  float4 v = *(const float4*)&src[off];
  *(__half2*)&dst[off] = __floats2half2_rn(v.x, v.y);
  *(__half2*)&dst[off + 2] = __floats2half2_rn(v.z, v.w);
}

// ------------- cumsum (scaled by L2E) -------------
__global__ void cumsum_kernel(const float* __restrict__ rpe) {
  int n = blockIdx.x, t = threadIdx.x, lane = t & 31, w = t >> 5;
  __shared__ float ws[8];
  float v[8];
  const float* row = rpe + n * S_;
#pragma unroll
  for (int j = 0; j < 8; j++) v[j] = row[t * 8 + j];
#pragma unroll
  for (int j = 1; j < 8; j++) v[j] += v[j - 1];
  float s = v[7];
#pragma unroll
  for (int o = 1; o < 32; o <<= 1) {
    float x = __shfl_up_sync(0xffffffffu, s, o);
    if (lane >= o) s += x;
  }
  if (lane == 31) ws[w] = s;
  __syncthreads();
  if (w == 0) {
    float x = (lane < 8) ? ws[lane] : 0.f;
#pragma unroll
    for (int o = 1; o < 8; o <<= 1) {
      float y = __shfl_up_sync(0xffffffffu, x, o);
      if (lane >= o) x += y;
    }
    if (lane < 8) ws[lane] = x;
  }
  __syncthreads();
  float off = s - v[7] + (w ? ws[w - 1] : 0.f);
#pragma unroll
  for (int j = 0; j < 8; j++) g_cum[n * S_ + t * 8 + j] = (v[j] + off) * L2E;
}

// ------------- fp16 GEMM, 128x128 tile, cp.async 3-stage ring, ONE sync/step -------------
// dyn smem: 3 x (A 128x40 + B 32x136) halves = 56832 B
// MODE 0: x[4096,1024]@w[1024,3072] -> fp16 q/k/v planes (q scaled L2E/8)
// MODE 1: mix(planes)[4096,1024]@ow[1024,1024] -> fp32 d_out
template <int MODE>
__global__ __launch_bounds__(256) void gemm_kernel(float* __restrict__ outp) {
  constexpr int Nn = (MODE == 0) ? QKVN : H_;
  const __half* __restrict__ Ag = (MODE == 0) ? g_xf : g_mixf;
  const __half* __restrict__ Bg = (MODE == 0) ? g_wf : g_owf;

  extern __shared__ __align__(16) __half gsm[];
#define GSA(st) (gsm + (st) * 5120)                // 128 x 40
#define GSB(st) (gsm + 15360 + (st) * 4352)        // 32 x 136

  const int tid = threadIdx.x, w = tid >> 5, lane = tid & 31;
  const int wm = w & 3, wn = w >> 2;
  const int row0 = blockIdx.y * 128, col0 = blockIdx.x * 128;

  float acc[2][8][4];
#pragma unroll
  for (int a = 0; a < 2; a++)
#pragma unroll
    for (int b = 0; b < 8; b++)
#pragma unroll
      for (int c = 0; c < 4; c++) acc[a][b][c] = 0.f;

  auto load_tile = [&](int st, int kt) {
#pragma unroll
    for (int p = 0; p < 2; p++) {  // A 128x32
      int i = tid + 256 * p;
      int r = i >> 2, seg = i & 3;
      int rg = row0 + r;
      long off;
      if (MODE == 0) {
        off = (long)rg * H_ + kt + seg * 8;
      } else {
        int k = kt + seg * 8;
        off = ((long)((rg >> 11) * N_ + (k >> 6)) * S_ + (rg & 2047)) * D_ + (k & 63);
      }
      cpa(sma(GSA(st) + r * 40 + seg * 8), &Ag[off]);
    }
#pragma unroll
    for (int p = 0; p < 2; p++) {  // B 32x128
      int i = tid + 256 * p;
      int r = i >> 4, c8 = i & 15;
      cpa(sma(GSB(st) + r * 136 + c8 * 8), &Bg[(long)(kt + r) * Nn + col0 + c8 * 8]);
    }
  };

  constexpr int NK = H_ / 32;
  load_tile(0, 0);
  cpcommit();
  load_tile(1, 32);
  cpcommit();
  for (int t = 0; t < NK; t++) {
    cpwait<1>();       // tile t landed
    __syncthreads();   // all warps done reading stage (t-1)%3
    if (t + 2 < NK) load_tile((t + 2) % 3, (t + 2) * 32);
    cpcommit();
    const int st = t % 3;
#pragma unroll
    for (int kc = 0; kc < 2; kc++) {
      uint32_t af[2][4];
#pragma unroll
      for (int mi = 0; mi < 2; mi++) {
        int r = wm * 32 + mi * 16 + (lane & 15);
        ldsm4(af[mi], sma(GSA(st) + r * 40 + kc * 16 + (lane >> 4) * 8));
      }
#pragma unroll
      for (int pr = 0; pr < 4; pr++) {
        uint32_t b4[4];
        int g = lane >> 3, r = lane & 7;
        int rb = kc * 16 + r + ((g & 1) ? 8 : 0);
        int cb = wn * 64 + pr * 16 + ((g >= 2) ? 8 : 0);
        ldsm4t(b4, sma(GSB(st) + rb * 136 + cb));
#pragma unroll
        for (int mi = 0; mi < 2; mi++) {
          mma_h(acc[mi][2 * pr], af[mi], b4[0], b4[1]);
          mma_h(acc[mi][2 * pr + 1], af[mi], b4[2], b4[3]);
        }
      }
    }
  }
  // epilogue: paired (v, v+1) -> adjacent columns, vectorized stores
#pragma unroll
  for (int mi = 0; mi < 2; mi++)
#pragma unroll
    for (int nj = 0; nj < 8; nj++)
#pragma unroll
      for (int vr = 0; vr < 2; vr++) {
        int rg = row0 + wm * 32 + mi * 16 + (lane >> 2) + vr * 8;
        int c = col0 + wn * 64 + nj * 8 + 2 * (lane & 3);
        float v0 = acc[mi][nj][2 * vr], v1 = acc[mi][nj][2 * vr + 1];
        if (MODE == 0) {
          int m = c >> 10, nh = (c >> 6) & 15, d = c & 63;
          if (m == 0) { v0 *= 0.125f * L2E; v1 *= 0.125f * L2E; }
          int b = rg >> 11, s = rg & 2047;
          long idx = ((long)(m * 32 + b * 16 + nh)) * PLANE + (long)s * D_ + d;
          *(__half2*)&g_qkvf[idx] = __floats2half2_rn(v0, v1);
        } else {
          float2 f2 = make_float2(v0, v1);
          *(float2*)&outp[(long)rg * H_ + c] = f2;
        }
      }
}

// ------------- causal flash attention: 3-stage KV ring, ONE sync per tile -------------
// dyn smem: 3 stages x (K 64x72 + V 64x72) = 55296 B; Q overlaps stage 0+1.
__global__ __launch_bounds__(256, 2) void flash_kernel() {
  extern __shared__ __align__(16) __half dsm[];
  __shared__ float sBias[2][192];
  const int qt = 15 - blockIdx.x;
  const int bh = blockIdx.y;
  const int n = bh & 15;
  const int q0 = qt * 128;
  const int tid = threadIdx.x, w = tid >> 5, lane = tid & 31;

  __half* sQ = dsm;  // 128x72 = 9216 halves (stage 0+1 region)
#define SK(st) (dsm + (st) * 9216)
#define SV(st) (dsm + (st) * 9216 + 4608)

  const long pl = (long)bh * PLANE;
  const __half* qg = g_qkvf + pl;
  const __half* kg = g_qkvf + MPLANE + pl;
  const __half* vg = g_qkvf + 2 * MPLANE + pl;

#pragma unroll
  for (int p = 0; p < 4; p++) {
    int i = tid + 256 * p;
    int r = i >> 3, c8 = i & 7;
    *(uint4*)&sQ[r * 72 + c8 * 8] = *(const uint4*)&qg[(long)(q0 + r) * D_ + c8 * 8];
  }
  __syncthreads();
  uint32_t qf[4][4];
  {
    int r = w * 16 + (lane & 15), cb = (lane >> 4) * 8;
#pragma unroll
    for (int kc = 0; kc < 4; kc++) ldsm4(qf[kc], sma(&sQ[r * 72 + kc * 16 + cb]));
  }
  __syncthreads();  // Q consumed; KV ring may overwrite

  float Oa[8][4];
#pragma unroll
  for (int j = 0; j < 8; j++)
#pragma unroll
    for (int v = 0; v < 4; v++) Oa[j][v] = 0.f;
  float mrow[2] = {-1e30f, -1e30f}, lrow[2] = {0.f, 0.f};
  const float* cumn = g_cum + n * S_;
  const int ntiles = 2 * qt + 2;
  const int itop = q0 + w * 16 + 15;
  const int ibase = w * 16 + (lane >> 2) + 63 - 2 * (lane & 3);
  constexpr uint32_t ONE2 = 0x3C003C00u;

  auto loadkv = [&](int st, int t) {
    int kv0 = t * 64;
#pragma unroll
    for (int p = 0; p < 2; p++) {
      int i = tid + 256 * p;
      int r = i >> 3, c8 = i & 7;
      long g = (long)(kv0 + r) * D_ + c8 * 8;
      cpa(sma(SK(st) + r * 72 + c8 * 8), kg + g);
      cpa(sma(SV(st) + r * 72 + c8 * 8), vg + g);
    }
  };
  auto stage_bias = [&](int buf, int t) {
    if (tid < 192) {
      int src = q0 - t * 64 - 63 + tid;
      sBias[buf][tid] = (src >= 0) ? cumn[src] : 0.f;
    }
  };

  loadkv(0, 0);
  cpcommit();
  loadkv(1, 1);
  cpcommit();
  stage_bias(0, 0);

  for (int t = 0; t < ntiles; t++) {
    const int kv0 = t * 64;
    cpwait<1>();
    __syncthreads();
    if (t + 2 < ntiles) loadkv((t + 2) % 3, t + 2);
    cpcommit();
    if (t + 1 < ntiles) stage_bias((t + 1) & 1, t + 1);
    const int st = t % 3;
    if (kv0 <= itop) {
      const float* bias = sBias[t & 1];
      float sc[8][4];
#pragma unroll
      for (int j = 0; j < 8; j++)
#pragma unroll
        for (int v = 0; v < 4; v++) sc[j][v] = 0.f;
#pragma unroll
      for (int kc = 0; kc < 4; kc++) {
#pragma unroll
        for (int pr = 0; pr < 4; pr++) {
          uint32_t b4[4];
          int g = lane >> 3, r = lane & 7;
          int rk = pr * 16 + r + ((g >= 2) ? 8 : 0);
          int ck = kc * 16 + ((g & 1) ? 8 : 0);
          ldsm4(b4, sma(SK(st) + rk * 72 + ck));
          mma_h(sc[2 * pr], qf[kc], b4[0], b4[1]);
          mma_h(sc[2 * pr + 1], qf[kc], b4[2], b4[3]);
        }
      }
      const bool full = (kv0 + 63 <= q0 + w * 16);
      const int dshift = q0 - kv0 - 63;
      float mx[2] = {-1e30f, -1e30f};
      if (full) {
#pragma unroll
        for (int j = 0; j < 8; j++)
#pragma unroll
          for (int v = 0; v < 4; v++) {
            int idx = ibase + ((v & 2) ? 8 : 0) - j * 8 - (v & 1);
            float s = sc[j][v] + bias[idx];
            sc[j][v] = s;
            mx[v >> 1] = fmaxf(mx[v >> 1], s);
          }
      } else {
#pragma unroll
        for (int j = 0; j < 8; j++)
#pragma unroll
          for (int v = 0; v < 4; v++) {
            int idx = ibase + ((v & 2) ? 8 : 0) - j * 8 - (v & 1);
            float s = (dshift + idx < 0) ? -1e30f : sc[j][v] + bias[idx];
            sc[j][v] = s;
            mx[v >> 1] = fmaxf(mx[v >> 1], s);
          }
      }
#pragma unroll
      for (int h = 0; h < 2; h++) {
        mx[h] = fmaxf(mx[h], __shfl_xor_sync(0xffffffffu, mx[h], 1));
        mx[h] = fmaxf(mx[h], __shfl_xor_sync(0xffffffffu, mx[h], 2));
      }
      float al[2];
#pragma unroll
      for (int h = 0; h < 2; h++) {
        float mn = fmaxf(mrow[h], mx[h]);
        al[h] = e2(mrow[h] - mn);
        mrow[h] = mn;
      }
      uint32_t ap[4][4];
#pragma unroll
      for (int kc = 0; kc < 4; kc++) {
        ap[kc][0] = h2ex2(pack2h(sc[2 * kc][0] - mrow[0], sc[2 * kc][1] - mrow[0]));
        ap[kc][1] = h2ex2(pack2h(sc[2 * kc][2] - mrow[1], sc[2 * kc][3] - mrow[1]));
        ap[kc][2] = h2ex2(pack2h(sc[2 * kc + 1][0] - mrow[0], sc[2 * kc + 1][1] - mrow[0]));
        ap[kc][3] = h2ex2(pack2h(sc[2 * kc + 1][2] - mrow[1], sc[2 * kc + 1][3] - mrow[1]));
      }
      float ps[4] = {0.f, 0.f, 0.f, 0.f};
#pragma unroll
      for (int kc = 0; kc < 4; kc++) mma_h(ps, ap[kc], ONE2, ONE2);
      lrow[0] = lrow[0] * al[0] + ps[0];
      lrow[1] = lrow[1] * al[1] + ps[2];
#pragma unroll
      for (int j = 0; j < 8; j++)
#pragma unroll
        for (int v = 0; v < 4; v++) Oa[j][v] *= al[v >> 1];
#pragma unroll
      for (int kc = 0; kc < 4; kc++) {
#pragma unroll
        for (int pr = 0; pr < 4; pr++) {
          uint32_t b4[4];
          int g = lane >> 3, r = lane & 7;
          int rv = kc * 16 + r + ((g & 1) ? 8 : 0);
          int cv = pr * 16 + ((g >= 2) ? 8 : 0);
          ldsm4t(b4, sma(SV(st) + rv * 72 + cv));
          mma_h(Oa[2 * pr], ap[kc], b4[0], b4[1]);
          mma_h(Oa[2 * pr + 1], ap[kc], b4[2], b4[3]);
        }
      }
    }
  }
  float inv[2] = {1.f / lrow[0], 1.f / lrow[1]};
  __half* mf = g_mixf + pl;
#pragma unroll
  for (int j = 0; j < 8; j++)
#pragma unroll
    for (int v = 0; v < 2; v++) {
      int ii = q0 + w * 16 + (lane >> 2) + v * 8;
      int d = j * 8 + 2 * (lane & 3);
      __half2 h = __floats2half2_rn(Oa[j][2 * v] * inv[v], Oa[j][2 * v + 1] * inv[v]);
      *(__half2*)&mf[(long)ii * D_ + d] = h;
    }
}

// ------------- launch -------------
extern "C" void kernel_launch(void* const* d_in, const int* in_sizes, int n_in,
                              void* d_out, int out_size) {
  const float* x = (const float*)d_in[0];
  const float* qkv = (const float*)d_in[1];
  const float* ow = (const float*)d_in[2];
  const float* rpe = (const float*)d_in[3];
  float* out = (float*)d_out;

  static cudaStream_t s2 = nullptr;
  static cudaEvent_t ev1 = nullptr, ev2 = nullptr;
  if (!s2) {
    cudaFuncSetAttribute(flash_kernel, cudaFuncAttributeMaxDynamicSharedMemorySize, 55296);
    cudaFuncSetAttribute(gemm_kernel<0>, cudaFuncAttributeMaxDynamicSharedMemorySize, 56832);
    cudaFuncSetAttribute(gemm_kernel<1>, cudaFuncAttributeMaxDynamicSharedMemorySize, 56832);
    cudaStreamCreateWithFlags(&s2, cudaStreamNonBlocking);
    cudaEventCreateWithFlags(&ev1, cudaEventDisableTiming);
    cudaEventCreateWithFlags(&ev2, cudaEventDisableTiming);
  }

  // fork: cumsum runs on s2 concurrently with convert+gemm0
  cudaEventRecord(ev1, 0);
  cudaStreamWaitEvent(s2, ev1, 0);
  cumsum_kernel<<<16, 256, 0, s2>>>(rpe);
  cudaEventRecord(ev2, s2);

  convert_all_kernel<<<(XN + WN + OWN) / 4 / 256, 256>>>(x, qkv, ow);
  gemm_kernel<0><<<dim3(QKVN / 128, MROWS / 128), 256, 56832>>>(nullptr);
  cudaStreamWaitEvent(0, ev2, 0);  // flash needs g_cum
  flash_kernel<<<dim3(16, B_ * N_), 256, 55296>>>();
  gemm_kernel<1><<<dim3(H_ / 128, MROWS / 128), 256, 56832>>>(out);
}